// round 12
// baseline (speedup 1.0000x reference)
#include <cuda_runtime.h>

// CANN recurrent net as a 14-node CUDA graph with Programmatic Dependent Launch.
//   step t (t=1..13): y = J @ s_{t-1};  U = y/recSum_{t-1} + Iext;  s_t=(0.2U)^2
//   step 14 (fused):  same, plus per-row tokens {tag|s}; a 149th collector CTA
//                     in the SAME grid polls the tokens and emits recSum_14 and
//                     r_14 = s_14/recSum_14 (saves the former final-node hop).
//
// Geometry (best measured): 148 CTAs x 384 threads, 1 warp = 1 row,
// launch_dependents after J-prefetch issue, regs <= 84 so predecessor +
// successor waves are fully co-resident (prefetch hidden).

#define Nn     1680
#define NBLK   148
#define TPB    384          // 12 warps
#define ITERS  14
#define KC     0.005f

__device__ float              g_s[2][Nn];    // unnormalized s vectors (t=1..13)
__device__ unsigned long long g_fin[Nn];     // step-14 tokens {tag:32 | s-bits:32}
__device__ unsigned           g_fin_seq;     // run sequence (collector increments)

__device__ __forceinline__ void pdl_wait() {
    asm volatile("griddepcontrol.wait;" ::: "memory");
}
__device__ __forceinline__ void pdl_launch_dependents() {
    asm volatile("griddepcontrol.launch_dependents;" ::: "memory");
}
__device__ __forceinline__ float4 ldcg4(const float4* p) {
    float4 v;
    asm volatile("ld.global.cg.v4.f32 {%0,%1,%2,%3}, [%4];"
                 : "=f"(v.x), "=f"(v.y), "=f"(v.z), "=f"(v.w) : "l"(p));
    return v;
}
__device__ __forceinline__ unsigned long long ldcg64(const unsigned long long* p) {
    unsigned long long v;
    asm volatile("ld.global.cg.u64 %0, [%1];" : "=l"(v) : "l"(p));
    return v;
}
__device__ __forceinline__ void stcg64(unsigned long long* p, unsigned long long v) {
    asm volatile("st.global.cg.u64 [%0], %1;" :: "l"(p), "l"(v) : "memory");
}
__device__ __forceinline__ unsigned ldcg32(const unsigned* p) {
    unsigned v;
    asm volatile("ld.global.cg.u32 %0, [%1];" : "=r"(v) : "l"(p));
    return v;
}
__device__ __forceinline__ void stcg32(unsigned* p, unsigned v) {
    asm volatile("st.global.cg.u32 [%0], %1;" :: "l"(p), "r"(v) : "memory");
}

// Shared worker body: stage s_{t-1}, matvec with fused recSum, emit s_t.
// publish_token = true only for t = ITERS.
__device__ __forceinline__ void step_body(const float* __restrict__ net_in,
                                          const float* __restrict__ J,
                                          float* __restrict__ out,
                                          int t, unsigned fin_tag)
{
    __shared__ __align__(16) float s_sm[Nn];

    const int tid  = threadIdx.x;
    const int lane = tid & 31;
    const int wid  = tid >> 5;
    const int row  = wid * NBLK + (int)blockIdx.x;   // 12*148 = 1776 >= 1680
    const bool active = (row < Nn);

    // ---- prefetch (independent of predecessor): J row -> regs, Iext ----
    float4 Jr[13];
    float jtail = 0.f, iext = 0.f;
    if (active) {
        iext = __ldg(&net_in[row]);
        const float* Jrow = J + (size_t)row * Nn;
        const float4* Jp = reinterpret_cast<const float4*>(Jrow);
        #pragma unroll
        for (int j = 0; j < 13; ++j) Jr[j] = __ldg(&Jp[j * 32 + lane]);
        if (lane < 16) jtail = __ldg(&Jrow[1664 + lane]);
    }

    if (t == 1) {   // launch-constant input: stage before the wait
        const float4* r4 = reinterpret_cast<const float4*>(net_in + Nn);
        #pragma unroll
        for (int k = 0; k < 2; ++k) {
            int i = tid + k * TPB;
            if (i < Nn / 4) reinterpret_cast<float4*>(s_sm)[i] = __ldg(&r4[i]);
        }
    }

    pdl_launch_dependents();   // gate opens after our loads are queued
    pdl_wait();                // predecessor's g_s writes now visible

    if (t != 1) {
        const float4* sp = reinterpret_cast<const float4*>(g_s[(t - 1) & 1]);
        #pragma unroll
        for (int k = 0; k < 2; ++k) {
            int i = tid + k * TPB;
            if (i < Nn / 4) reinterpret_cast<float4*>(s_sm)[i] = ldcg4(&sp[i]);
        }
    }
    __syncthreads();

    if (active) {
        const float4* s4 = reinterpret_cast<const float4*>(s_sm);
        float a0 = 0.f, a1 = 0.f, rs = 0.f;
        #pragma unroll
        for (int j = 0; j < 13; ++j) {
            float4 b = s4[j * 32 + lane];
            rs += (b.x + b.y) + (b.z + b.w);
            if (j & 1) {
                a1 = fmaf(Jr[j].x, b.x, a1); a1 = fmaf(Jr[j].y, b.y, a1);
                a1 = fmaf(Jr[j].z, b.z, a1); a1 = fmaf(Jr[j].w, b.w, a1);
            } else {
                a0 = fmaf(Jr[j].x, b.x, a0); a0 = fmaf(Jr[j].y, b.y, a0);
                a0 = fmaf(Jr[j].z, b.z, a0); a0 = fmaf(Jr[j].w, b.w, a0);
            }
        }
        if (lane < 16) {
            float bt = s_sm[1664 + lane];
            rs += bt;
            a1 = fmaf(jtail, bt, a1);
        }
        float acc = a0 + a1;
        #pragma unroll
        for (int o = 16; o; o >>= 1) {
            acc += __shfl_xor_sync(0xffffffffu, acc, o);
            rs  += __shfl_xor_sync(0xffffffffu, rs,  o);
        }
        if (lane == 0) {
            const float invDen = (t == 1) ? 1.0f : 1.0f / (KC * rs);
            float U  = fmaf(acc, invDen, iext);
            float u2 = 0.2f * U;
            float sv = u2 * u2;
            if (t == ITERS) {
                out[row] = U;                           // U_14
                stcg64(&g_fin[row],
                       ((unsigned long long)fin_tag << 32) |
                       (unsigned long long)__float_as_uint(sv));
            } else {
                g_s[t & 1][row] = sv;
            }
        }
    }
}

__global__ void __launch_bounds__(TPB, 2)
step_kernel(const float* __restrict__ net_in,
            const float* __restrict__ J,
            float* __restrict__ out,
            int t)
{
    step_body(net_in, J, out, t, 0u);
}

// Step 14: grid = 149 CTAs. CTAs 0..147 are workers publishing tokens;
// CTA 148 collects, computes recSum_14, writes recSum_14 and r_14.
__global__ void __launch_bounds__(TPB, 2)
step14_kernel(const float* __restrict__ net_in,
              const float* __restrict__ J,
              float* __restrict__ out)
{
    if (blockIdx.x < NBLK) {
        const unsigned tag = ldcg32(&g_fin_seq) + 1u;   // stable all run
        step_body(net_in, J, out, ITERS, tag);
        return;
    }

    // ---- collector CTA ----
    __shared__ float s_part[12];
    const int tid  = threadIdx.x;
    const int lane = tid & 31;
    const int wid  = tid >> 5;

    pdl_launch_dependents();   // keep the gate semantics uniform
    const unsigned target = ldcg32(&g_fin_seq) + 1u;

    // Slots: tid + k*384, k = 0..4 (1680 = 4*384 + 144; tid<144 own 5).
    const int cnt = (tid < Nn - 4 * TPB) ? 5 : 4;
    const unsigned need = (1u << cnt) - 1u;
    float vals[5] = {0.f, 0.f, 0.f, 0.f, 0.f};
    unsigned done = 0;
    while (done != need) {
        unsigned long long v[5];
        const unsigned pend = need & ~done;
        #pragma unroll
        for (int k = 0; k < 5; ++k)
            if (pend & (1u << k)) v[k] = ldcg64(&g_fin[tid + k * TPB]);
        #pragma unroll
        for (int k = 0; k < 5; ++k)
            if ((pend & (1u << k)) && (unsigned)(v[k] >> 32) == target) {
                vals[k] = __uint_as_float((unsigned)v[k]);
                done |= 1u << k;
            }
    }

    // Deterministic fixed-order reduction.
    float loc = ((vals[0] + vals[1]) + (vals[2] + vals[3])) + vals[4];
    #pragma unroll
    for (int o = 16; o; o >>= 1) loc += __shfl_xor_sync(0xffffffffu, loc, o);
    if (lane == 0) s_part[wid] = loc;
    __syncthreads();
    float tot = 0.f;
    #pragma unroll
    for (int w = 0; w < 12; ++w) tot += s_part[w];
    const float recS = KC * tot;

    if (tid == 0) out[Nn] = recS;                        // recSum_14
    #pragma unroll
    for (int k = 0; k < 5; ++k)                          // r_14
        if (k < cnt) out[Nn + 1 + tid + k * TPB] = vals[k] / recS;

    __syncthreads();
    if (tid == 0) stcg32(&g_fin_seq, target);            // advance run sequence
}

extern "C" void kernel_launch(void* const* d_in, const int* in_sizes, int n_in,
                              void* d_out, int out_size)
{
    const float* a = (const float*)d_in[0];
    const float* b = (const float*)d_in[1];
    const float* net_in = a;
    const float* J      = b;
    if (n_in >= 2 && in_sizes[0] > in_sizes[1]) { net_in = b; J = a; }
    float* out = (float*)d_out;

    cudaLaunchAttribute attr[1];
    attr[0].id = cudaLaunchAttributeProgrammaticStreamSerialization;
    attr[0].val.programmaticStreamSerializationAllowed = 1;

    cudaLaunchConfig_t cfg = {};
    cfg.gridDim  = dim3(NBLK, 1, 1);
    cfg.blockDim = dim3(TPB, 1, 1);
    cfg.dynamicSmemBytes = 0;
    cfg.stream = 0;            // legacy default stream (captured by harness)
    cfg.attrs = attr;
    cfg.numAttrs = 1;

    for (int t = 1; t <= ITERS - 1; ++t)
        cudaLaunchKernelEx(&cfg, step_kernel, net_in, J, out, t);

    cudaLaunchConfig_t cfg14 = cfg;
    cfg14.gridDim = dim3(NBLK + 1, 1, 1);
    cudaLaunchKernelEx(&cfg14, step14_kernel, net_in, J, out);
}